// round 2
// baseline (speedup 1.0000x reference)
#include <cuda_runtime.h>
#include <math.h>

// Problem constants
#define SS   512
#define BB   64
#define DD   1024
#define HH   1024
#define LL   2
#define K4   4096              // 4*H
#define SB   (SS*BB)           // 32768
#define SBH  ((size_t)SS*BB*HH) // 33554432
#define BH   (BB*HH)           // 65536
#define NBLK 128               // persistent scan grid (<= 148 SMs -> co-resident)

// ---------------- device scratch (no allocations allowed) ----------------
__device__ float   g_xg[(size_t)SB * K4];   // 512 MB: precomputed x@wx + bias for current layer
__device__ float   g_x1[SBH];               // 128 MB: layer-0 output sequence (input to layer 1)
__device__ float   g_h[BH];                 // current hidden state
__device__ float   g_c[BH];                 // current cell state
__device__ float   g_gates[BB * K4];        // per-step gate buffer (1 MB)
__device__ unsigned g_count = 0;            // grid barrier counter
__device__ unsigned g_gen   = 0;            // grid barrier generation

// ---------------- helpers ----------------
__device__ __forceinline__ float sigf(float x) { return 1.0f / (1.0f + expf(-x)); }

// Software grid barrier: valid because all NBLK blocks are resident.
__device__ __forceinline__ void grid_sync_(unsigned nblocks, unsigned& gen) {
    __syncthreads();
    if (threadIdx.x == 0) {
        __threadfence();
        unsigned t = atomicAdd(&g_count, 1u);
        if (t == nblocks - 1u) {
            atomicExch(&g_count, 0u);
            __threadfence();
            atomicExch(&g_gen, gen + 1u);
        } else {
            while (*((volatile unsigned*)&g_gen) == gen) { __nanosleep(64); }
            __threadfence();
        }
        gen += 1u;
    }
    __syncthreads();
}

// ---------------- input GEMM: C[M=32768, N=4096] = A[M,1024] * W[1024,4096] + bias ----------------
__global__ void __launch_bounds__(256) gemm_xg_kernel(
    const float* __restrict__ Ain, int layer,
    const float* __restrict__ W, const float* __restrict__ bias)
{
    const float* __restrict__ A = (layer == 0) ? Ain : (const float*)g_x1;
    __shared__ float As[64][33];
    __shared__ float Ws[32][64];

    const int tid = threadIdx.x;
    const int ty = tid >> 4, tx = tid & 15;
    const int row0 = blockIdx.y * 64;
    const int col0 = blockIdx.x * 64;

    float acc[4][4] = {};

    for (int k0 = 0; k0 < 1024; k0 += 32) {
        #pragma unroll
        for (int j = 0; j < 8; ++j) {                 // 64x32 A tile
            int e = tid + j * 256;
            int r = e >> 5, kk = e & 31;
            As[r][kk] = A[(size_t)(row0 + r) * 1024 + (k0 + kk)];
        }
        #pragma unroll
        for (int j = 0; j < 8; ++j) {                 // 32x64 W tile
            int e = tid + j * 256;
            int kk = e >> 6, n = e & 63;
            Ws[kk][n] = W[(size_t)(k0 + kk) * 4096 + (col0 + n)];
        }
        __syncthreads();
        #pragma unroll
        for (int kk = 0; kk < 32; ++kk) {
            float4 w = *(const float4*)&Ws[kk][tx * 4];
            float a0 = As[ty*4+0][kk], a1 = As[ty*4+1][kk];
            float a2 = As[ty*4+2][kk], a3 = As[ty*4+3][kk];
            acc[0][0] += a0*w.x; acc[0][1] += a0*w.y; acc[0][2] += a0*w.z; acc[0][3] += a0*w.w;
            acc[1][0] += a1*w.x; acc[1][1] += a1*w.y; acc[1][2] += a1*w.z; acc[1][3] += a1*w.w;
            acc[2][0] += a2*w.x; acc[2][1] += a2*w.y; acc[2][2] += a2*w.z; acc[2][3] += a2*w.w;
            acc[3][0] += a3*w.x; acc[3][1] += a3*w.y; acc[3][2] += a3*w.z; acc[3][3] += a3*w.w;
        }
        __syncthreads();
    }

    #pragma unroll
    for (int r = 0; r < 4; ++r) {
        int row = row0 + ty * 4 + r;
        #pragma unroll
        for (int c = 0; c < 4; ++c) {
            int col = col0 + tx * 4 + c;
            g_xg[(size_t)row * 4096 + col] = acc[r][c] + bias[col];
        }
    }
}

// ---------------- state init ----------------
__global__ void init_state_kernel(const float* __restrict__ h0, const float* __restrict__ c0) {
    int i = blockIdx.x * blockDim.x + threadIdx.x;
    if (i < BH) { g_h[i] = h0[i]; g_c[i] = c0[i]; }
}

// ---------------- persistent recurrent scan ----------------
// Phase A: gates[64,4096] = xg[t] + h @ wh   (128 blocks, each 64x32 tile)
// Phase B: per-batch-row LayerNorm over 4 gate groups + LSTM cell update (blocks 0..63)
__global__ void __launch_bounds__(256) lstm_scan_kernel(
    const float* __restrict__ wh,      // [1024, 4096] for this layer
    const float* __restrict__ gamma,   // [4, 1024]
    const float* __restrict__ beta,    // [4, 1024]
    float* __restrict__ ysExt,         // layer-1: final output x region
    int layer,
    float* __restrict__ outh,          // d_out hs slot for this layer
    float* __restrict__ outc)          // d_out cs slot for this layer
{
    __shared__ float Hs[64][33];
    __shared__ float Ws2[32][32];
    __shared__ float s_red[16];
    __shared__ float s_mu[4], s_rs[4];

    const int bid = blockIdx.x;
    const int tid = threadIdx.x;
    const int ty = tid >> 4, tx = tid & 15;
    const int col0 = bid * 32;

    float* __restrict__ ys = (layer == 0) ? (float*)g_x1 : ysExt;

    unsigned gen = *((volatile unsigned*)&g_gen);   // stable: prior launch completed

    for (int t = 0; t < SS; ++t) {
        // ----- Phase A: gate GEMM tile (64 rows x 32 cols), K=1024 -----
        float acc[4][2];
        #pragma unroll
        for (int r = 0; r < 4; ++r)
            #pragma unroll
            for (int c = 0; c < 2; ++c)
                acc[r][c] = g_xg[((size_t)t * 64 + (ty*4 + r)) * 4096 + col0 + tx*2 + c];

        for (int k0 = 0; k0 < 1024; k0 += 32) {
            #pragma unroll
            for (int j = 0; j < 8; ++j) {             // h tile 64x32
                int e = tid + j * 256;
                int r = e >> 5, kk = e & 31;
                Hs[r][kk] = g_h[r * 1024 + (k0 + kk)];
            }
            #pragma unroll
            for (int j = 0; j < 4; ++j) {             // wh tile 32x32
                int e = tid + j * 256;
                int kk = e >> 5, c = e & 31;
                Ws2[kk][c] = wh[(size_t)(k0 + kk) * 4096 + col0 + c];
            }
            __syncthreads();
            #pragma unroll
            for (int kk = 0; kk < 32; ++kk) {
                float2 w = *(const float2*)&Ws2[kk][tx * 2];
                float a0 = Hs[ty*4+0][kk], a1 = Hs[ty*4+1][kk];
                float a2 = Hs[ty*4+2][kk], a3 = Hs[ty*4+3][kk];
                acc[0][0] += a0*w.x; acc[0][1] += a0*w.y;
                acc[1][0] += a1*w.x; acc[1][1] += a1*w.y;
                acc[2][0] += a2*w.x; acc[2][1] += a2*w.y;
                acc[3][0] += a3*w.x; acc[3][1] += a3*w.y;
            }
            __syncthreads();
        }
        #pragma unroll
        for (int r = 0; r < 4; ++r)
            #pragma unroll
            for (int c = 0; c < 2; ++c)
                g_gates[(ty*4 + r) * 4096 + col0 + tx*2 + c] = acc[r][c];

        grid_sync_(NBLK, gen);

        // ----- Phase B: LayerNorm + cell update (one block per batch row) -----
        if (bid < BB) {
            const float* __restrict__ grow = g_gates + bid * 4096;
            for (int g = 0; g < 4; ++g) {
                const float* __restrict__ gp = grow + g * 1024;
                float s = 0.f, s2 = 0.f;
                #pragma unroll
                for (int j = 0; j < 4; ++j) {
                    float v = gp[tid + j * 256];
                    s += v; s2 += v * v;
                }
                #pragma unroll
                for (int o = 16; o > 0; o >>= 1) {
                    s  += __shfl_down_sync(0xFFFFFFFFu, s,  o);
                    s2 += __shfl_down_sync(0xFFFFFFFFu, s2, o);
                }
                int w = tid >> 5, lane = tid & 31;
                if (lane == 0) { s_red[w] = s; s_red[8 + w] = s2; }
                __syncthreads();
                if (tid == 0) {
                    float ts = 0.f, ts2 = 0.f;
                    #pragma unroll
                    for (int i = 0; i < 8; ++i) { ts += s_red[i]; ts2 += s_red[8 + i]; }
                    float mu  = ts * (1.0f / 1024.0f);
                    float var = ts2 * (1.0f / 1024.0f) - mu * mu;
                    s_mu[g] = mu;
                    s_rs[g] = rsqrtf(var + 1e-5f);
                }
                __syncthreads();
            }
            for (int h = tid; h < 1024; h += 256) {
                float iv = (grow[h       ] - s_mu[0]) * s_rs[0] * gamma[h       ] + beta[h       ];
                float fv = (grow[1024 + h] - s_mu[1]) * s_rs[1] * gamma[1024 + h] + beta[1024 + h];
                float ov = (grow[2048 + h] - s_mu[2]) * s_rs[2] * gamma[2048 + h] + beta[2048 + h];
                float uv = (grow[3072 + h] - s_mu[3]) * s_rs[3] * gamma[3072 + h] + beta[3072 + h];
                float cp = g_c[bid * 1024 + h];
                float cn = sigf(fv) * cp + sigf(iv) * tanhf(uv);
                float hn = sigf(ov) * tanhf(cn);
                g_c[bid * 1024 + h] = cn;
                g_h[bid * 1024 + h] = hn;
                ys[((size_t)t * 64 + bid) * 1024 + h] = hn;
                if (t == SS - 1) {
                    outh[bid * 1024 + h] = hn;
                    outc[bid * 1024 + h] = cn;
                }
            }
        }

        grid_sync_(NBLK, gen);
    }
}

// ---------------- launch ----------------
extern "C" void kernel_launch(void* const* d_in, const int* in_sizes, int n_in,
                              void* d_out, int out_size)
{
    const float* inputs = (const float*)d_in[0];  // (S,B,D)
    const float* h0     = (const float*)d_in[1];  // (L,B,H)
    const float* c0     = (const float*)d_in[2];  // (L,B,H)
    const float* wx     = (const float*)d_in[3];  // (L,D,4H)
    const float* wh     = (const float*)d_in[4];  // (L,H,4H)
    const float* bias   = (const float*)d_in[5];  // (L,4H)
    const float* gamma  = (const float*)d_in[6];  // (L,4,H)
    const float* beta   = (const float*)d_in[7];  // (L,4,H)

    float* out   = (float*)d_out;
    float* out_x = out;                         // (S,B,H)
    float* out_h = out + SBH;                   // (L,B,H)
    float* out_c = out_h + (size_t)LL * BH;     // (L,B,H)

    dim3 ggrid(K4 / 64, SB / 64);               // (64, 512)

    for (int l = 0; l < LL; ++l) {
        gemm_xg_kernel<<<ggrid, 256>>>(inputs, l,
                                       wx + (size_t)l * DD * K4,
                                       bias + (size_t)l * K4);
        init_state_kernel<<<(BH + 255) / 256, 256>>>(h0 + (size_t)l * BH,
                                                     c0 + (size_t)l * BH);
        lstm_scan_kernel<<<NBLK, 256>>>(wh + (size_t)l * HH * K4,
                                        gamma + (size_t)l * 4 * HH,
                                        beta  + (size_t)l * 4 * HH,
                                        out_x, l,
                                        out_h + (size_t)l * BH,
                                        out_c + (size_t)l * BH);
    }
}

// round 6
// speedup vs baseline: 1.2789x; 1.2789x over previous
#include <cuda_runtime.h>
#include <math.h>

// Problem constants
#define SS   512
#define BB   64
#define DD   1024
#define HH   1024
#define LL   2
#define K4   4096
#define SB   (SS*BB)
#define SBH  ((size_t)SS*BB*HH)
#define BH   (BB*HH)
#define NBLK 128

typedef unsigned long long ull;

// packed fp32x2 FMA (Blackwell sm_103a): d = a*b + d elementwise on 2 floats
#define FMA2(d, a, b) asm("fma.rn.f32x2 %0, %1, %2, %0;" : "+l"(d) : "l"(a), "l"(b))

__device__ __forceinline__ float pairsum(ull v) {
    float lo, hi;
    asm("mov.b64 {%0, %1}, %2;" : "=f"(lo), "=f"(hi) : "l"(v));
    return lo + hi;
}

// ---------------- device scratch ----------------
__device__ float   g_xg[(size_t)SB * K4];    // 512 MB: x@wx + bias for current layer
__device__ float   g_x1[SBH];                // 128 MB: layer-0 output sequence
__device__ float   g_h[BH];
__device__ float   g_c[BH];
__device__ float   g_part[2 * BB * K4];      // split-K partial gate sums (2 MB)
__device__ unsigned g_count = 0;
__device__ unsigned g_gen   = 0;

__device__ __forceinline__ float sigf(float x) { return 1.0f / (1.0f + expf(-x)); }

__device__ __forceinline__ void grid_sync_(unsigned nblocks, unsigned& gen) {
    __syncthreads();
    if (threadIdx.x == 0) {
        __threadfence();
        unsigned t = atomicAdd(&g_count, 1u);
        if (t == nblocks - 1u) {
            atomicExch(&g_count, 0u);
            __threadfence();
            atomicExch(&g_gen, gen + 1u);
        } else {
            while (*((volatile unsigned*)&g_gen) == gen) { __nanosleep(32); }
            __threadfence();
        }
        gen += 1u;
    }
    __syncthreads();
}

// ================= input GEMM: g_xg[M=32768,4096] = A[M,1024]*W[1024,4096] + bias =================
// tile 128x64, BK=16, 256 threads, micro 8 rows x 4 cols, k-packed f32x2
__global__ void __launch_bounds__(256) gemm_xg_kernel(
    const float* __restrict__ Ain, int layer,
    const float* __restrict__ W, const float* __restrict__ bias)
{
    const float* __restrict__ A = (layer == 0) ? Ain : (const float*)g_x1;
    __shared__ __align__(16) float  As[2][128][20];     // rows x k (padded)
    __shared__ __align__(16) float2 Ws[2][8][64];       // kpair x col

    const int tid = threadIdx.x;
    const int tx = tid & 15;
    const int ry = (tid >> 4) * 8;
    const int row0 = blockIdx.y * 128;
    const int col0 = blockIdx.x * 64;

    // fill coords
    const int fr = tid >> 2, fk = (tid & 3) * 4;        // A: rows fr, fr+64
    const int wk = tid >> 4, wc = (tid & 15) * 4;       // W: row wk, cols wc..wc+3
    const int wp = wk >> 1, wo = wk & 1;

    ull acc[8][4];
    #pragma unroll
    for (int i = 0; i < 8; ++i)
        #pragma unroll
        for (int j = 0; j < 4; ++j) acc[i][j] = 0ULL;

    float4 pa0, pa1, pw;
    // LDG stage 0
    pa0 = *(const float4*)&A[(size_t)(row0 + fr)      * 1024 + fk];
    pa1 = *(const float4*)&A[(size_t)(row0 + fr + 64) * 1024 + fk];
    pw  = *(const float4*)&W[(size_t)wk * 4096 + col0 + wc];
    // STS stage 0
    {
        *(float4*)&As[0][fr][fk]      = pa0;
        *(float4*)&As[0][fr + 64][fk] = pa1;
        float2* wr = Ws[0][wp];
        if (wo == 0) { wr[wc].x = pw.x; wr[wc+1].x = pw.y; wr[wc+2].x = pw.z; wr[wc+3].x = pw.w; }
        else         { wr[wc].y = pw.x; wr[wc+1].y = pw.y; wr[wc+2].y = pw.z; wr[wc+3].y = pw.w; }
    }
    __syncthreads();

    #pragma unroll 1
    for (int s = 0; s < 64; ++s) {
        const int buf = s & 1;
        if (s < 63) {
            const int k0 = (s + 1) * 16;
            pa0 = *(const float4*)&A[(size_t)(row0 + fr)      * 1024 + k0 + fk];
            pa1 = *(const float4*)&A[(size_t)(row0 + fr + 64) * 1024 + k0 + fk];
            pw  = *(const float4*)&W[(size_t)(k0 + wk) * 4096 + col0 + wc];
        }
        #pragma unroll
        for (int q = 0; q < 4; ++q) {
            ull a0[8], a1[8];
            #pragma unroll
            for (int i = 0; i < 8; ++i) {
                ulonglong2 t = *(const ulonglong2*)&As[buf][ry + i][q * 4];
                a0[i] = t.x; a1[i] = t.y;
            }
            ull w0[4], w1[4];
            #pragma unroll
            for (int j = 0; j < 4; ++j) {
                w0[j] = *(const ull*)&Ws[buf][2*q    ][tx + 16*j];
                w1[j] = *(const ull*)&Ws[buf][2*q + 1][tx + 16*j];
            }
            #pragma unroll
            for (int i = 0; i < 8; ++i)
                #pragma unroll
                for (int j = 0; j < 4; ++j) {
                    FMA2(acc[i][j], a0[i], w0[j]);
                    FMA2(acc[i][j], a1[i], w1[j]);
                }
        }
        if (s < 63) {
            const int nb = (s + 1) & 1;
            *(float4*)&As[nb][fr][fk]      = pa0;
            *(float4*)&As[nb][fr + 64][fk] = pa1;
            float2* wr = Ws[nb][wp];
            if (wo == 0) { wr[wc].x = pw.x; wr[wc+1].x = pw.y; wr[wc+2].x = pw.z; wr[wc+3].x = pw.w; }
            else         { wr[wc].y = pw.x; wr[wc+1].y = pw.y; wr[wc+2].y = pw.z; wr[wc+3].y = pw.w; }
        }
        __syncthreads();
    }

    #pragma unroll
    for (int i = 0; i < 8; ++i) {
        const size_t rbase = (size_t)(row0 + ry + i) * 4096;
        #pragma unroll
        for (int j = 0; j < 4; ++j) {
            const int col = col0 + tx + 16*j;
            g_xg[rbase + col] = pairsum(acc[i][j]) + bias[col];
        }
    }
}

// ---------------- state init ----------------
__global__ void init_state_kernel(const float* __restrict__ h0, const float* __restrict__ c0) {
    int i = blockIdx.x * blockDim.x + threadIdx.x;
    if (i < BH) { g_h[i] = h0[i]; g_c[i] = c0[i]; }
}

// ================= persistent recurrent scan =================
// Phase A: 128 blocks = 64 coltiles x 2 k-halves; tile 64 rows x 64 cols, K=512 each,
//          micro 4x4, k-packed f32x2. Partial sums -> g_part[khalf].
// Phase B: 128 blocks = 64 rows x 2 halves; LN (two-pass var) + cell update.
__global__ void __launch_bounds__(256) lstm_scan_kernel(
    const float* __restrict__ wh,
    const float* __restrict__ gamma,
    const float* __restrict__ beta,
    float* __restrict__ ysExt, int layer,
    float* __restrict__ outh, float* __restrict__ outc)
{
    __shared__ __align__(16) char smraw[18432 + 256];
    float*  As   = (float*)smraw;               // [2][64][20] = 10240 B
    float2* Ws   = (float2*)(smraw + 10240);    // [2][8][64]  =  8192 B
    float*  brow = (float*)smraw;               // [4096]      = 16384 B (phase B)
    float*  bred = (float*)(smraw + 16384);     // [32]
    float*  bmu  = (float*)(smraw + 16384 + 128);
    float*  brs  = (float*)(smraw + 16384 + 160);

    const int tid = threadIdx.x, bid = blockIdx.x;
    const int lane = tid & 31, warp = tid >> 5;
    const int tx = tid & 15;
    const int ry = (tid >> 4) * 4;
    const int coltile = bid >> 1, khalf = bid & 1;
    const int col0 = coltile * 64;
    const int kbase = khalf * 512;
    const int row = bid >> 1, half = bid & 1;   // phase-B role

    const int fr = tid >> 2, fk = (tid & 3) * 4;
    const int wk = tid >> 4, wc = (tid & 15) * 4;
    const int wp = wk >> 1, wo = wk & 1;

    float* __restrict__ ys = (layer == 0) ? (float*)g_x1 : ysExt;
    float* __restrict__ pOut = g_part + (size_t)khalf * BB * K4;

    unsigned gen = *((volatile unsigned*)&g_gen);

    for (int t = 0; t < SS; ++t) {
        // ----- Phase A -----
        ull acc[4][4];
        #pragma unroll
        for (int i = 0; i < 4; ++i)
            #pragma unroll
            for (int j = 0; j < 4; ++j) acc[i][j] = 0ULL;

        float4 pa, pw;
        pa = *(const float4*)&g_h[fr * 1024 + kbase + fk];
        pw = *(const float4*)&wh[(size_t)(kbase + wk) * 4096 + col0 + wc];
        {
            *(float4*)&As[fr * 20 + fk] = pa;
            float2* wr = &Ws[(size_t)wp * 64];
            if (wo == 0) { wr[wc].x = pw.x; wr[wc+1].x = pw.y; wr[wc+2].x = pw.z; wr[wc+3].x = pw.w; }
            else         { wr[wc].y = pw.x; wr[wc+1].y = pw.y; wr[wc+2].y = pw.z; wr[wc+3].y = pw.w; }
        }
        __syncthreads();

        #pragma unroll 1
        for (int s = 0; s < 32; ++s) {
            const int buf = s & 1;
            if (s < 31) {
                const int k0 = kbase + (s + 1) * 16;
                pa = *(const float4*)&g_h[fr * 1024 + k0 + fk];
                pw = *(const float4*)&wh[(size_t)(k0 + wk) * 4096 + col0 + wc];
            }
            const float*  Ab = As + buf * 1280;
            const float2* Wb = Ws + buf * 512;
            #pragma unroll
            for (int q = 0; q < 4; ++q) {
                ull a0[4], a1[4];
                #pragma unroll
                for (int i = 0; i < 4; ++i) {
                    ulonglong2 tt = *(const ulonglong2*)&Ab[(ry + i) * 20 + q * 4];
                    a0[i] = tt.x; a1[i] = tt.y;
                }
                ull w0[4], w1[4];
                #pragma unroll
                for (int j = 0; j < 4; ++j) {
                    w0[j] = *(const ull*)&Wb[(2*q    ) * 64 + tx + 16*j];
                    w1[j] = *(const ull*)&Wb[(2*q + 1) * 64 + tx + 16*j];
                }
                #pragma unroll
                for (int i = 0; i < 4; ++i)
                    #pragma unroll
                    for (int j = 0; j < 4; ++j) {
                        FMA2(acc[i][j], a0[i], w0[j]);
                        FMA2(acc[i][j], a1[i], w1[j]);
                    }
            }
            if (s < 31) {
                const int nb = (s + 1) & 1;
                *(float4*)&As[nb * 1280 + fr * 20 + fk] = pa;
                float2* wr = &Ws[(size_t)nb * 512 + (size_t)wp * 64];
                if (wo == 0) { wr[wc].x = pw.x; wr[wc+1].x = pw.y; wr[wc+2].x = pw.z; wr[wc+3].x = pw.w; }
                else         { wr[wc].y = pw.x; wr[wc+1].y = pw.y; wr[wc+2].y = pw.z; wr[wc+3].y = pw.w; }
            }
            __syncthreads();
        }

        #pragma unroll
        for (int i = 0; i < 4; ++i)
            #pragma unroll
            for (int j = 0; j < 4; ++j)
                pOut[(ry + i) * 4096 + col0 + tx + 16*j] = pairsum(acc[i][j]);

        grid_sync_(NBLK, gen);

        // ----- Phase B: LN + cell update -----
        {
            const float* __restrict__ pA  = g_part + row * 4096;
            const float* __restrict__ pB  = g_part + BB * K4 + row * 4096;
            const float* __restrict__ xgr = g_xg + ((size_t)t * 64 + row) * 4096;

            float gv[16];
            #pragma unroll
            for (int k = 0; k < 16; ++k) {
                const int c = tid + (k << 8);
                float v = pA[c] + pB[c] + xgr[c];
                gv[k] = v;
                brow[c] = v;
            }
            // pass 1: means per gate group (group = k>>2)
            float s4[4] = {0.f, 0.f, 0.f, 0.f};
            #pragma unroll
            for (int k = 0; k < 16; ++k) s4[k >> 2] += gv[k];
            #pragma unroll
            for (int o = 16; o > 0; o >>= 1) {
                #pragma unroll
                for (int g = 0; g < 4; ++g) s4[g] += __shfl_xor_sync(0xFFFFFFFFu, s4[g], o);
            }
            if (lane == 0) {
                #pragma unroll
                for (int g = 0; g < 4; ++g) bred[warp * 4 + g] = s4[g];
            }
            __syncthreads();
            if (tid < 4) {
                float tot = 0.f;
                #pragma unroll
                for (int w = 0; w < 8; ++w) tot += bred[w * 4 + tid];
                bmu[tid] = tot * (1.0f / 1024.0f);
            }
            __syncthreads();
            float m0 = bmu[0], m1 = bmu[1], m2 = bmu[2], m3 = bmu[3];
            const float mm[4] = {m0, m1, m2, m3};
            // pass 2: centered variance
            float q4[4] = {0.f, 0.f, 0.f, 0.f};
            #pragma unroll
            for (int k = 0; k < 16; ++k) {
                float d = gv[k] - mm[k >> 2];
                q4[k >> 2] = fmaf(d, d, q4[k >> 2]);
            }
            #pragma unroll
            for (int o = 16; o > 0; o >>= 1) {
                #pragma unroll
                for (int g = 0; g < 4; ++g) q4[g] += __shfl_xor_sync(0xFFFFFFFFu, q4[g], o);
            }
            if (lane == 0) {
                #pragma unroll
                for (int g = 0; g < 4; ++g) bred[warp * 4 + g] = q4[g];
            }
            __syncthreads();
            if (tid < 4) {
                float tot = 0.f;
                #pragma unroll
                for (int w = 0; w < 8; ++w) tot += bred[w * 4 + tid];
                brs[tid] = rsqrtf(tot * (1.0f / 1024.0f) + 1e-5f);
            }
            __syncthreads();
            float r0 = brs[0], r1 = brs[1], r2 = brs[2], r3 = brs[3];
            m0 = bmu[0]; m1 = bmu[1]; m2 = bmu[2]; m3 = bmu[3];

            const int cbase = half * 512 + tid * 2;
            #pragma unroll
            for (int e = 0; e < 2; ++e) {
                const int c = cbase + e;
                float iv = (brow[c       ] - m0) * r0 * gamma[c       ] + beta[c       ];
                float fv = (brow[1024 + c] - m1) * r1 * gamma[1024 + c] + beta[1024 + c];
                float ov = (brow[2048 + c] - m2) * r2 * gamma[2048 + c] + beta[2048 + c];
                float uv = (brow[3072 + c] - m3) * r3 * gamma[3072 + c] + beta[3072 + c];
                float cp = g_c[row * 1024 + c];
                float cn = sigf(fv) * cp + sigf(iv) * tanhf(uv);
                float hn = sigf(ov) * tanhf(cn);
                g_c[row * 1024 + c] = cn;
                g_h[row * 1024 + c] = hn;
                ys[((size_t)t * 64 + row) * 1024 + c] = hn;
                if (t == SS - 1) {
                    outh[row * 1024 + c] = hn;
                    outc[row * 1024 + c] = cn;
                }
            }
        }

        grid_sync_(NBLK, gen);
    }
}

// ---------------- launch ----------------
extern "C" void kernel_launch(void* const* d_in, const int* in_sizes, int n_in,
                              void* d_out, int out_size)
{
    const float* inputs = (const float*)d_in[0];
    const float* h0     = (const float*)d_in[1];
    const float* c0     = (const float*)d_in[2];
    const float* wx     = (const float*)d_in[3];
    const float* wh     = (const float*)d_in[4];
    const float* bias   = (const float*)d_in[5];
    const float* gamma  = (const float*)d_in[6];
    const float* beta   = (const float*)d_in[7];

    float* out   = (float*)d_out;
    float* out_x = out;
    float* out_h = out + SBH;
    float* out_c = out_h + (size_t)LL * BH;

    dim3 ggrid(K4 / 64, SB / 128);   // (64, 256)

    for (int l = 0; l < LL; ++l) {
        gemm_xg_kernel<<<ggrid, 256>>>(inputs, l,
                                       wx + (size_t)l * DD * K4,
                                       bias + (size_t)l * K4);
        init_state_kernel<<<(BH + 255) / 256, 256>>>(h0 + (size_t)l * BH,
                                                     c0 + (size_t)l * BH);
        lstm_scan_kernel<<<NBLK, 256>>>(wh + (size_t)l * HH * K4,
                                        gamma + (size_t)l * 4 * HH,
                                        beta  + (size_t)l * 4 * HH,
                                        out_x, l,
                                        out_h + (size_t)l * BH,
                                        out_c + (size_t)l * BH);
    }
}

// round 10
// speedup vs baseline: 1.4069x; 1.1001x over previous
#include <cuda_runtime.h>
#include <math.h>

// Problem constants
#define SS   512
#define BB   64
#define DD   1024
#define HH   1024
#define LL   2
#define K4   4096
#define SB   (SS*BB)
#define SBH  ((size_t)SS*BB*HH)
#define BH   (BB*HH)
#define NBLK 128

typedef unsigned long long ull;

// packed fp32x2 FMA (Blackwell sm_103a)
#define FMA2(d, a, b) asm("fma.rn.f32x2 %0, %1, %2, %0;" : "+l"(d) : "l"(a), "l"(b))

// cp.async 16B
#define CP16(dst_u32, src_ptr) \
    asm volatile("cp.async.cg.shared.global [%0], [%1], 16;" :: "r"(dst_u32), "l"(src_ptr))
#define CPCOMMIT() asm volatile("cp.async.commit_group;")
#define CPWAIT1()  asm volatile("cp.async.wait_group 1;")
#define CPWAIT0()  asm volatile("cp.async.wait_group 0;")

__device__ __forceinline__ float pairsum(ull v) {
    float lo, hi;
    asm("mov.b64 {%0, %1}, %2;" : "=f"(lo), "=f"(hi) : "l"(v));
    return lo + hi;
}

// ---------------- device scratch ----------------
__device__ float   g_xg[(size_t)SB * K4];     // 512 MB
__device__ float   g_x1[SBH];                 // 128 MB
__device__ float2  g_wxp[512 * 4096];         // 16 MB: packed wx (current layer)
__device__ float2  g_whp[512 * 4096];         // 16 MB: packed wh (current layer)
__device__ float   g_h[BH];
__device__ float   g_c[BH];
__device__ float   g_part[2 * BB * K4];
__device__ unsigned g_count = 0;
__device__ unsigned g_gen   = 0;

__device__ __forceinline__ float sigf(float x) { return 1.0f / (1.0f + expf(-x)); }

__device__ __forceinline__ void grid_sync_(unsigned nblocks, unsigned& gen) {
    __syncthreads();
    if (threadIdx.x == 0) {
        __threadfence();
        unsigned t = atomicAdd(&g_count, 1u);
        if (t == nblocks - 1u) {
            atomicExch(&g_count, 0u);
            __threadfence();
            atomicExch(&g_gen, gen + 1u);
        } else {
            while (*((volatile unsigned*)&g_gen) == gen) { __nanosleep(32); }
            __threadfence();
        }
        gen += 1u;
    }
    __syncthreads();
}

// ---------------- weight pre-pack: dst[kp*4096+c] = {W[2kp][c], W[2kp+1][c]} ----------------
// which: 0 -> g_wxp, 1 -> g_whp.  (Device symbols MUST be resolved in device code,
// never passed as host-side kernel arguments -- that was the R8 bug.)
__global__ void __launch_bounds__(256) pack_weights_kernel(
    const float* __restrict__ W, int which)
{
    float2* __restrict__ out = which ? g_whp : g_wxp;
    int i = blockIdx.x * blockDim.x + threadIdx.x;   // over 512*4096
    int kp = i >> 12, c = i & 4095;
    out[i] = make_float2(W[(size_t)(2 * kp) * 4096 + c],
                         W[(size_t)(2 * kp + 1) * 4096 + c]);
}

// ================= input GEMM: g_xg[32768,4096] = A[.,1024]*W + bias =================
// tile 128x64, BK=16 (8 kpairs), 256 threads, 2 blocks/SM, micro 8 rows x 4 cols
__global__ void __launch_bounds__(256, 2) gemm_xg_kernel(
    const float* __restrict__ Ain, int layer, const float* __restrict__ bias)
{
    const float* __restrict__ A = (layer == 0) ? Ain : (const float*)g_x1;
    const float2* __restrict__ Wp = (const float2*)g_wxp;

    __shared__ __align__(16) float  As[2][128][20];
    __shared__ __align__(16) float2 Wt[2][8][64];

    const int tid = threadIdx.x;
    const int tx = tid & 15;
    const int ry = (tid >> 4) * 8;
    const int row0 = blockIdx.y * 128;
    const int col0 = blockIdx.x * 64;

    const int fr = tid >> 2, fk = (tid & 3) * 4;      // A fill: rows fr, fr+64
    const int wr = tid >> 5, wc = (tid & 31) * 2;     // W fill: kpair row wr, float2 cols wc..wc+1

    const unsigned sA0a = (unsigned)__cvta_generic_to_shared(&As[0][fr][fk]);
    const unsigned sA0b = (unsigned)__cvta_generic_to_shared(&As[0][fr + 64][fk]);
    const unsigned sW0  = (unsigned)__cvta_generic_to_shared(&Wt[0][wr][wc]);
    const unsigned aStride = 128 * 20 * 4;            // bytes between As buffers
    const unsigned wStride = 8 * 64 * 8;              // bytes between Wt buffers

    ull acc[8][4];
    #pragma unroll
    for (int i = 0; i < 8; ++i)
        #pragma unroll
        for (int j = 0; j < 4; ++j) acc[i][j] = 0ULL;

    // prologue: stage 0
    CP16(sA0a, &A[(size_t)(row0 + fr) * 1024 + fk]);
    CP16(sA0b, &A[(size_t)(row0 + fr + 64) * 1024 + fk]);
    CP16(sW0,  &Wp[(size_t)wr * 4096 + col0 + wc]);
    CPCOMMIT();

    #pragma unroll 1
    for (int s = 0; s < 64; ++s) {
        const int buf = s & 1;
        if (s < 63) {
            const int nb = (s + 1) & 1;
            const int k0 = (s + 1) * 16;
            const int kp0 = (s + 1) * 8;
            CP16(sA0a + nb * aStride, &A[(size_t)(row0 + fr) * 1024 + k0 + fk]);
            CP16(sA0b + nb * aStride, &A[(size_t)(row0 + fr + 64) * 1024 + k0 + fk]);
            CP16(sW0  + nb * wStride, &Wp[(size_t)(kp0 + wr) * 4096 + col0 + wc]);
            CPCOMMIT();
            CPWAIT1();
        } else {
            CPWAIT0();
        }
        __syncthreads();

        #pragma unroll
        for (int q = 0; q < 4; ++q) {
            ulonglong2 w0a = *(const ulonglong2*)&Wt[buf][2*q    ][2 * tx];
            ulonglong2 w0b = *(const ulonglong2*)&Wt[buf][2*q    ][2 * tx + 32];
            ulonglong2 w1a = *(const ulonglong2*)&Wt[buf][2*q + 1][2 * tx];
            ulonglong2 w1b = *(const ulonglong2*)&Wt[buf][2*q + 1][2 * tx + 32];
            #pragma unroll
            for (int i = 0; i < 8; ++i) {
                ulonglong2 a = *(const ulonglong2*)&As[buf][ry + i][4 * q];
                FMA2(acc[i][0], a.x, w0a.x);  FMA2(acc[i][1], a.x, w0a.y);
                FMA2(acc[i][2], a.x, w0b.x);  FMA2(acc[i][3], a.x, w0b.y);
                FMA2(acc[i][0], a.y, w1a.x);  FMA2(acc[i][1], a.y, w1a.y);
                FMA2(acc[i][2], a.y, w1b.x);  FMA2(acc[i][3], a.y, w1b.y);
            }
        }
        __syncthreads();
    }

    const float b0 = bias[col0 + 2*tx],      b1 = bias[col0 + 2*tx + 1];
    const float b2 = bias[col0 + 2*tx + 32], b3 = bias[col0 + 2*tx + 33];
    #pragma unroll
    for (int i = 0; i < 8; ++i) {
        const size_t rbase = (size_t)(row0 + ry + i) * 4096 + col0;
        *(float2*)&g_xg[rbase + 2*tx]      = make_float2(pairsum(acc[i][0]) + b0, pairsum(acc[i][1]) + b1);
        *(float2*)&g_xg[rbase + 2*tx + 32] = make_float2(pairsum(acc[i][2]) + b2, pairsum(acc[i][3]) + b3);
    }
}

// ---------------- state init ----------------
__global__ void init_state_kernel(const float* __restrict__ h0, const float* __restrict__ c0) {
    int i = blockIdx.x * blockDim.x + threadIdx.x;
    if (i < BH) { g_h[i] = h0[i]; g_c[i] = c0[i]; }
}

// ================= persistent recurrent scan =================
// 128 blocks = 64 coltiles x 2 k-halves. wh slice (256 kpair x 64 col, 128KB) resident in smem.
// Phase A: tile 64x64, K=512, BK=32, micro 4x4, cp.async double-buffered h chunks.
// Phase B: blocks = 64 rows x 2 halves; LN (two-pass var) + cell update.
__global__ void __launch_bounds__(256) lstm_scan_kernel(
    const float* __restrict__ gamma,
    const float* __restrict__ beta,
    float* __restrict__ ysExt, int layer,
    float* __restrict__ outh, float* __restrict__ outc)
{
    extern __shared__ __align__(16) char sm[];
    float2* Wsm  = (float2*)sm;                         // [256][64] = 131072 B
    float*  Hs   = (float*)(sm + 131072);               // [2][64][36] = 18432 B
    float*  brow = (float*)(sm + 131072);               // alias (phase B, 16384 B)
    float*  bred = (float*)(sm + 131072 + 18432);       // 32 floats
    float*  bmu  = bred + 32;
    float*  brs  = bred + 36;

    const int tid = threadIdx.x, bid = blockIdx.x;
    const int lane = tid & 31, warp = tid >> 5;
    const int tx = tid & 15;
    const int ry = (tid >> 4) * 4;
    const int coltile = bid >> 1, khalf = bid & 1;
    const int col0 = coltile * 64;
    const int kb = khalf * 256;                          // kpair base
    const int kbase = khalf * 512;                       // float k base
    const int row = bid >> 1, half = bid & 1;            // phase-B role

    const int hr = tid >> 3, hc = (tid & 7) * 4;         // h fill: rows hr, hr+32

    float* __restrict__ ys = (layer == 0) ? (float*)g_x1 : ysExt;
    float* __restrict__ pOut = g_part + (size_t)khalf * BB * K4;

    // load wh slice into smem once (packed layout)
    for (int i = tid; i < 256 * 64; i += 256) {
        int kp = i >> 6, c = i & 63;
        Wsm[i] = g_whp[(size_t)(kb + kp) * 4096 + col0 + c];
    }
    __syncthreads();

    const unsigned sH0a = (unsigned)__cvta_generic_to_shared(&Hs[hr * 36 + hc]);
    const unsigned sH0b = (unsigned)__cvta_generic_to_shared(&Hs[(hr + 32) * 36 + hc]);
    const unsigned hStride = 64 * 36 * 4;

    unsigned gen = *((volatile unsigned*)&g_gen);

    for (int t = 0; t < SS; ++t) {
        // ----- Phase A -----
        ull acc[4][4];
        #pragma unroll
        for (int i = 0; i < 4; ++i)
            #pragma unroll
            for (int j = 0; j < 4; ++j) acc[i][j] = 0ULL;

        // prologue: h chunk 0
        CP16(sH0a, &g_h[hr * 1024 + kbase + hc]);
        CP16(sH0b, &g_h[(hr + 32) * 1024 + kbase + hc]);
        CPCOMMIT();

        #pragma unroll 1
        for (int s = 0; s < 16; ++s) {
            const int buf = s & 1;
            if (s < 15) {
                const int nb = (s + 1) & 1;
                const int k0 = kbase + (s + 1) * 32;
                CP16(sH0a + nb * hStride, &g_h[hr * 1024 + k0 + hc]);
                CP16(sH0b + nb * hStride, &g_h[(hr + 32) * 1024 + k0 + hc]);
                CPCOMMIT();
                CPWAIT1();
            } else {
                CPWAIT0();
            }
            __syncthreads();

            const float* Hb = Hs + buf * (64 * 36);
            const int kpofs = s * 16;
            #pragma unroll
            for (int q = 0; q < 8; ++q) {
                ulonglong2 w0a = *(const ulonglong2*)&Wsm[(kpofs + 2*q    ) * 64 + 2 * tx];
                ulonglong2 w0b = *(const ulonglong2*)&Wsm[(kpofs + 2*q    ) * 64 + 2 * tx + 32];
                ulonglong2 w1a = *(const ulonglong2*)&Wsm[(kpofs + 2*q + 1) * 64 + 2 * tx];
                ulonglong2 w1b = *(const ulonglong2*)&Wsm[(kpofs + 2*q + 1) * 64 + 2 * tx + 32];
                #pragma unroll
                for (int i = 0; i < 4; ++i) {
                    ulonglong2 a = *(const ulonglong2*)&Hb[(ry + i) * 36 + 4 * q];
                    FMA2(acc[i][0], a.x, w0a.x);  FMA2(acc[i][1], a.x, w0a.y);
                    FMA2(acc[i][2], a.x, w0b.x);  FMA2(acc[i][3], a.x, w0b.y);
                    FMA2(acc[i][0], a.y, w1a.x);  FMA2(acc[i][1], a.y, w1a.y);
                    FMA2(acc[i][2], a.y, w1b.x);  FMA2(acc[i][3], a.y, w1b.y);
                }
            }
            __syncthreads();
        }

        #pragma unroll
        for (int i = 0; i < 4; ++i) {
            const size_t rbase = (size_t)(ry + i) * 4096 + col0;
            *(float2*)&pOut[rbase + 2*tx]      = make_float2(pairsum(acc[i][0]), pairsum(acc[i][1]));
            *(float2*)&pOut[rbase + 2*tx + 32] = make_float2(pairsum(acc[i][2]), pairsum(acc[i][3]));
        }

        grid_sync_(NBLK, gen);

        // ----- Phase B: LN + cell update -----
        {
            const float* __restrict__ pA  = g_part + row * 4096;
            const float* __restrict__ pB  = g_part + BB * K4 + row * 4096;
            const float* __restrict__ xgr = g_xg + ((size_t)t * 64 + row) * 4096;

            float gv[16];
            #pragma unroll
            for (int k = 0; k < 16; ++k) {
                const int c = tid + (k << 8);
                float v = pA[c] + pB[c] + xgr[c];
                gv[k] = v;
                brow[c] = v;
            }
            float s4[4] = {0.f, 0.f, 0.f, 0.f};
            #pragma unroll
            for (int k = 0; k < 16; ++k) s4[k >> 2] += gv[k];
            #pragma unroll
            for (int o = 16; o > 0; o >>= 1) {
                #pragma unroll
                for (int g = 0; g < 4; ++g) s4[g] += __shfl_xor_sync(0xFFFFFFFFu, s4[g], o);
            }
            if (lane == 0) {
                #pragma unroll
                for (int g = 0; g < 4; ++g) bred[warp * 4 + g] = s4[g];
            }
            __syncthreads();
            if (tid < 4) {
                float tot = 0.f;
                #pragma unroll
                for (int w = 0; w < 8; ++w) tot += bred[w * 4 + tid];
                bmu[tid] = tot * (1.0f / 1024.0f);
            }
            __syncthreads();
            const float mm[4] = {bmu[0], bmu[1], bmu[2], bmu[3]};
            float q4[4] = {0.f, 0.f, 0.f, 0.f};
            #pragma unroll
            for (int k = 0; k < 16; ++k) {
                float d = gv[k] - mm[k >> 2];
                q4[k >> 2] = fmaf(d, d, q4[k >> 2]);
            }
            #pragma unroll
            for (int o = 16; o > 0; o >>= 1) {
                #pragma unroll
                for (int g = 0; g < 4; ++g) q4[g] += __shfl_xor_sync(0xFFFFFFFFu, q4[g], o);
            }
            if (lane == 0) {
                #pragma unroll
                for (int g = 0; g < 4; ++g) bred[warp * 4 + g] = q4[g];
            }
            __syncthreads();
            if (tid < 4) {
                float tot = 0.f;
                #pragma unroll
                for (int w = 0; w < 8; ++w) tot += bred[w * 4 + tid];
                brs[tid] = rsqrtf(tot * (1.0f / 1024.0f) + 1e-5f);
            }
            __syncthreads();
            const float r0 = brs[0], r1 = brs[1], r2 = brs[2], r3 = brs[3];
            const float m0 = bmu[0], m1 = bmu[1], m2 = bmu[2], m3 = bmu[3];

            const int cbase = half * 512 + tid * 2;
            #pragma unroll
            for (int e = 0; e < 2; ++e) {
                const int c = cbase + e;
                float iv = (brow[c       ] - m0) * r0 * gamma[c       ] + beta[c       ];
                float fv = (brow[1024 + c] - m1) * r1 * gamma[1024 + c] + beta[1024 + c];
                float ov = (brow[2048 + c] - m2) * r2 * gamma[2048 + c] + beta[2048 + c];
                float uv = (brow[3072 + c] - m3) * r3 * gamma[3072 + c] + beta[3072 + c];
                float cp = g_c[row * 1024 + c];
                float cn = sigf(fv) * cp + sigf(iv) * tanhf(uv);
                float hn = sigf(ov) * tanhf(cn);
                g_c[row * 1024 + c] = cn;
                g_h[row * 1024 + c] = hn;
                ys[((size_t)t * 64 + row) * 1024 + c] = hn;
                if (t == SS - 1) {
                    outh[row * 1024 + c] = hn;
                    outc[row * 1024 + c] = cn;
                }
            }
        }

        grid_sync_(NBLK, gen);
    }
}

// ---------------- launch ----------------
extern "C" void kernel_launch(void* const* d_in, const int* in_sizes, int n_in,
                              void* d_out, int out_size)
{
    const float* inputs = (const float*)d_in[0];
    const float* h0     = (const float*)d_in[1];
    const float* c0     = (const float*)d_in[2];
    const float* wx     = (const float*)d_in[3];
    const float* wh     = (const float*)d_in[4];
    const float* bias   = (const float*)d_in[5];
    const float* gamma  = (const float*)d_in[6];
    const float* beta   = (const float*)d_in[7];

    float* out   = (float*)d_out;
    float* out_x = out;
    float* out_h = out + SBH;
    float* out_c = out_h + (size_t)LL * BH;

    static const int SCAN_SMEM = 131072 + 18432 + 256;
    cudaFuncSetAttribute(lstm_scan_kernel,
                         cudaFuncAttributeMaxDynamicSharedMemorySize, SCAN_SMEM);

    dim3 ggrid(K4 / 64, SB / 128);    // (64, 256)
    const int packBlocks = (512 * 4096) / 256;

    for (int l = 0; l < LL; ++l) {
        pack_weights_kernel<<<packBlocks, 256>>>(wx + (size_t)l * DD * K4, 0);
        pack_weights_kernel<<<packBlocks, 256>>>(wh + (size_t)l * HH * K4, 1);
        gemm_xg_kernel<<<ggrid, 256>>>(inputs, l, bias + (size_t)l * K4);
        init_state_kernel<<<(BH + 255) / 256, 256>>>(h0 + (size_t)l * BH,
                                                     c0 + (size_t)l * BH);
        lstm_scan_kernel<<<NBLK, 256, SCAN_SMEM>>>(gamma + (size_t)l * 4 * HH,
                                                   beta  + (size_t)l * 4 * HH,
                                                   out_x, l,
                                                   out_h + (size_t)l * BH,
                                                   out_c + (size_t)l * BH);
    }
}

// round 13
// speedup vs baseline: 1.4333x; 1.0188x over previous
#include <cuda_runtime.h>
#include <math.h>

// Problem constants
#define SS   512
#define BB   64
#define DD   1024
#define HH   1024
#define LL   2
#define K4   4096
#define SB   (SS*BB)
#define SBH  ((size_t)SS*BB*HH)
#define BH   (BB*HH)
#define NBLK 128

typedef unsigned long long ull;

// packed fp32x2 FMA (Blackwell sm_103a)
#define FMA2(d, a, b) asm("fma.rn.f32x2 %0, %1, %2, %0;" : "+l"(d) : "l"(a), "l"(b))

// cp.async 16B
#define CP16(dst_u32, src_ptr) \
    asm volatile("cp.async.cg.shared.global [%0], [%1], 16;" :: "r"(dst_u32), "l"(src_ptr))
#define CPCOMMIT() asm volatile("cp.async.commit_group;")
#define CPWAIT1()  asm volatile("cp.async.wait_group 1;")
#define CPWAIT0()  asm volatile("cp.async.wait_group 0;")

__device__ __forceinline__ float pairsum(ull v) {
    float lo, hi;
    asm("mov.b64 {%0, %1}, %2;" : "=f"(lo), "=f"(hi) : "l"(v));
    return lo + hi;
}

// ---------------- device scratch ----------------
__device__ float   g_xg[(size_t)SB * K4];        // 512 MB
__device__ float   g_x1[SBH];                    // 128 MB
__device__ float2  g_wxp[LL][512 * 4096];        // 2 x 16 MB packed wx
__device__ float2  g_whp[LL][512 * 4096];        // 2 x 16 MB packed wh
__device__ float   g_h[BH];
__device__ float   g_c[BH];
__device__ float   g_part[2 * BB * K4];
__device__ unsigned g_sub[8];
__device__ unsigned g_master;
__device__ volatile unsigned g_gen2;

__device__ __forceinline__ float sigf(float x) { return 1.0f / (1.0f + expf(-x)); }

// Two-level grid barrier: 8 sub-counters (16 blocks each) -> master counter -> release.
__device__ __forceinline__ void grid_sync_(int bid, unsigned& gen) {
    __syncthreads();
    if (threadIdx.x == 0) {
        __threadfence();
        unsigned t = atomicAdd(&g_sub[bid & 7], 1u);
        if (t == 15u) {
            atomicExch(&g_sub[bid & 7], 0u);        // reset before master bump (pre-release => safe)
            unsigned m = atomicAdd(&g_master, 1u);
            if (m == 7u) {
                atomicExch(&g_master, 0u);
                __threadfence();
                g_gen2 = gen + 1u;                  // release
            }
        }
        while (g_gen2 == gen) { }
        __threadfence();
        gen += 1u;
    }
    __syncthreads();
}

// ---------------- weight pre-pack: dst[kp*4096+c] = {W[2kp][c], W[2kp+1][c]} ----------------
__global__ void __launch_bounds__(256) pack_weights_kernel(
    const float* __restrict__ W, int which, int layer)
{
    float2* __restrict__ out = which ? g_whp[layer] : g_wxp[layer];
    int i = blockIdx.x * blockDim.x + threadIdx.x;   // over 512*4096
    int kp = i >> 12, c = i & 4095;
    out[i] = make_float2(W[(size_t)(2 * kp) * 4096 + c],
                         W[(size_t)(2 * kp + 1) * 4096 + c]);
}

// ================= input GEMM: g_xg[32768,4096] = A[.,1024]*W + bias =================
// tile 128x64, BK=16 (8 kpairs), 256 threads, 2 blocks/SM, micro 8 rows x 4 cols
__global__ void __launch_bounds__(256, 2) gemm_xg_kernel(
    const float* __restrict__ Ain, int layer, const float* __restrict__ bias)
{
    const float* __restrict__ A = (layer == 0) ? Ain : (const float*)g_x1;
    const float2* __restrict__ Wp = g_wxp[layer];

    __shared__ __align__(16) float  As[2][128][20];
    __shared__ __align__(16) float2 Wt[2][8][64];

    const int tid = threadIdx.x;
    const int tx = tid & 15;
    const int ry = (tid >> 4) * 8;
    const int row0 = blockIdx.y * 128;
    const int col0 = blockIdx.x * 64;

    const int fr = tid >> 2, fk = (tid & 3) * 4;      // A fill: rows fr, fr+64
    const int wr = tid >> 5, wc = (tid & 31) * 2;     // W fill: kpair row wr, float2 cols wc..wc+1

    const unsigned sA0a = (unsigned)__cvta_generic_to_shared(&As[0][fr][fk]);
    const unsigned sA0b = (unsigned)__cvta_generic_to_shared(&As[0][fr + 64][fk]);
    const unsigned sW0  = (unsigned)__cvta_generic_to_shared(&Wt[0][wr][wc]);
    const unsigned aStride = 128 * 20 * 4;
    const unsigned wStride = 8 * 64 * 8;

    ull acc[8][4];
    #pragma unroll
    for (int i = 0; i < 8; ++i)
        #pragma unroll
        for (int j = 0; j < 4; ++j) acc[i][j] = 0ULL;

    CP16(sA0a, &A[(size_t)(row0 + fr) * 1024 + fk]);
    CP16(sA0b, &A[(size_t)(row0 + fr + 64) * 1024 + fk]);
    CP16(sW0,  &Wp[(size_t)wr * 4096 + col0 + wc]);
    CPCOMMIT();

    #pragma unroll 1
    for (int s = 0; s < 64; ++s) {
        const int buf = s & 1;
        if (s < 63) {
            const int nb = (s + 1) & 1;
            const int k0 = (s + 1) * 16;
            const int kp0 = (s + 1) * 8;
            CP16(sA0a + nb * aStride, &A[(size_t)(row0 + fr) * 1024 + k0 + fk]);
            CP16(sA0b + nb * aStride, &A[(size_t)(row0 + fr + 64) * 1024 + k0 + fk]);
            CP16(sW0  + nb * wStride, &Wp[(size_t)(kp0 + wr) * 4096 + col0 + wc]);
            CPCOMMIT();
            CPWAIT1();
        } else {
            CPWAIT0();
        }
        __syncthreads();

        #pragma unroll
        for (int q = 0; q < 4; ++q) {
            ulonglong2 w0a = *(const ulonglong2*)&Wt[buf][2*q    ][2 * tx];
            ulonglong2 w0b = *(const ulonglong2*)&Wt[buf][2*q    ][2 * tx + 32];
            ulonglong2 w1a = *(const ulonglong2*)&Wt[buf][2*q + 1][2 * tx];
            ulonglong2 w1b = *(const ulonglong2*)&Wt[buf][2*q + 1][2 * tx + 32];
            #pragma unroll
            for (int i = 0; i < 8; ++i) {
                ulonglong2 a = *(const ulonglong2*)&As[buf][ry + i][4 * q];
                FMA2(acc[i][0], a.x, w0a.x);  FMA2(acc[i][1], a.x, w0a.y);
                FMA2(acc[i][2], a.x, w0b.x);  FMA2(acc[i][3], a.x, w0b.y);
                FMA2(acc[i][0], a.y, w1a.x);  FMA2(acc[i][1], a.y, w1a.y);
                FMA2(acc[i][2], a.y, w1b.x);  FMA2(acc[i][3], a.y, w1b.y);
            }
        }
        __syncthreads();
    }

    const float b0 = bias[col0 + 2*tx],      b1 = bias[col0 + 2*tx + 1];
    const float b2 = bias[col0 + 2*tx + 32], b3 = bias[col0 + 2*tx + 33];
    #pragma unroll
    for (int i = 0; i < 8; ++i) {
        const size_t rbase = (size_t)(row0 + ry + i) * 4096 + col0;
        *(float2*)&g_xg[rbase + 2*tx]      = make_float2(pairsum(acc[i][0]) + b0, pairsum(acc[i][1]) + b1);
        *(float2*)&g_xg[rbase + 2*tx + 32] = make_float2(pairsum(acc[i][2]) + b2, pairsum(acc[i][3]) + b3);
    }
}

// ---------------- state init ----------------
__global__ void init_state_kernel(const float* __restrict__ h0, const float* __restrict__ c0) {
    int i = blockIdx.x * blockDim.x + threadIdx.x;
    if (i < BH) { g_h[i] = h0[i]; g_c[i] = c0[i]; }
}

// ================= persistent recurrent scan =================
// 128 blocks = 64 coltiles x 2 k-halves. wh slice (256 kpair x 64 col, 128KB) resident in smem.
// Phase A: tile 64x64, K=512, BK=64 (8 stages), micro 4x4, cp.async double-buffered h chunks.
// Phase B: blocks = 64 rows x 2 halves; LN (two-pass var) + cell update.
__global__ void __launch_bounds__(256) lstm_scan_kernel(
    const float* __restrict__ gamma,
    const float* __restrict__ beta,
    float* __restrict__ ysExt, int layer,
    float* __restrict__ outh, float* __restrict__ outc)
{
    extern __shared__ __align__(16) char sm[];
    float2* Wsm  = (float2*)sm;                         // [256][64] = 131072 B
    float*  Hs   = (float*)(sm + 131072);               // [2][64][68] = 34816 B
    float*  brow = (float*)(sm + 131072);               // alias (phase B, 16384 B)
    float*  bred = (float*)(sm + 131072 + 34816);       // 32 floats
    float*  bmu  = bred + 32;
    float*  brs  = bred + 36;

    const int tid = threadIdx.x, bid = blockIdx.x;
    const int lane = tid & 31, warp = tid >> 5;
    const int tx = tid & 15;
    const int ry = (tid >> 4) * 4;
    const int coltile = bid >> 1, khalf = bid & 1;
    const int col0 = coltile * 64;
    const int kb = khalf * 256;                          // kpair base
    const int kbase = khalf * 512;                       // float k base
    const int row = bid >> 1, half = bid & 1;            // phase-B role

    // h fill: row hr, CONTIGUOUS floats hk..hk+15 (4x CP16 stepping +4 floats).
    // R11 bug: the follow-up copies stepped +16 floats -> overlap + gaps.
    const int hr = tid >> 2, hk = (tid & 3) * 16;

    float* __restrict__ ys = (layer == 0) ? (float*)g_x1 : ysExt;
    float* __restrict__ pOut = g_part + (size_t)khalf * BB * K4;
    const float2* __restrict__ whp = g_whp[layer];

    // load wh slice into smem once (packed layout)
    for (int i = tid; i < 256 * 64; i += 256) {
        int kp = i >> 6, c = i & 63;
        Wsm[i] = whp[(size_t)(kb + kp) * 4096 + col0 + c];
    }
    __syncthreads();

    const unsigned sH0 = (unsigned)__cvta_generic_to_shared(&Hs[hr * 68 + hk]);
    const unsigned hStride = 64 * 68 * 4;                // 17408 B between buffers

    unsigned gen = g_gen2;

    for (int t = 0; t < SS; ++t) {
        // ----- Phase A -----
        ull acc[4][4];
        #pragma unroll
        for (int i = 0; i < 4; ++i)
            #pragma unroll
            for (int j = 0; j < 4; ++j) acc[i][j] = 0ULL;

        // prologue: h chunk 0 (64 k), contiguous 16-float span per thread
        {
            const float* src = &g_h[hr * 1024 + kbase + hk];
            CP16(sH0,      src);
            CP16(sH0 + 16, src + 4);
            CP16(sH0 + 32, src + 8);
            CP16(sH0 + 48, src + 12);
            CPCOMMIT();
        }

        #pragma unroll 1
        for (int s = 0; s < 8; ++s) {
            const int buf = s & 1;
            if (s < 7) {
                const int nb = (s + 1) & 1;
                const float* src = &g_h[hr * 1024 + kbase + (s + 1) * 64 + hk];
                const unsigned d = sH0 + nb * hStride;
                CP16(d,      src);
                CP16(d + 16, src + 4);
                CP16(d + 32, src + 8);
                CP16(d + 48, src + 12);
                CPCOMMIT();
                CPWAIT1();
            } else {
                CPWAIT0();
            }
            __syncthreads();

            const float* Hb = Hs + buf * (64 * 68);
            const int kpofs = s * 32;
            #pragma unroll
            for (int q = 0; q < 16; ++q) {
                ulonglong2 w0a = *(const ulonglong2*)&Wsm[(kpofs + 2*q    ) * 64 + 2 * tx];
                ulonglong2 w0b = *(const ulonglong2*)&Wsm[(kpofs + 2*q    ) * 64 + 2 * tx + 32];
                ulonglong2 w1a = *(const ulonglong2*)&Wsm[(kpofs + 2*q + 1) * 64 + 2 * tx];
                ulonglong2 w1b = *(const ulonglong2*)&Wsm[(kpofs + 2*q + 1) * 64 + 2 * tx + 32];
                #pragma unroll
                for (int i = 0; i < 4; ++i) {
                    ulonglong2 a = *(const ulonglong2*)&Hb[(ry + i) * 68 + 4 * q];
                    FMA2(acc[i][0], a.x, w0a.x);  FMA2(acc[i][1], a.x, w0a.y);
                    FMA2(acc[i][2], a.x, w0b.x);  FMA2(acc[i][3], a.x, w0b.y);
                    FMA2(acc[i][0], a.y, w1a.x);  FMA2(acc[i][1], a.y, w1a.y);
                    FMA2(acc[i][2], a.y, w1b.x);  FMA2(acc[i][3], a.y, w1b.y);
                }
            }
            __syncthreads();
        }

        #pragma unroll
        for (int i = 0; i < 4; ++i) {
            const size_t rbase = (size_t)(ry + i) * 4096 + col0;
            *(float2*)&pOut[rbase + 2*tx]      = make_float2(pairsum(acc[i][0]), pairsum(acc[i][1]));
            *(float2*)&pOut[rbase + 2*tx + 32] = make_float2(pairsum(acc[i][2]), pairsum(acc[i][3]));
        }

        grid_sync_(bid, gen);

        // ----- Phase B: LN + cell update -----
        {
            const float* __restrict__ pA  = g_part + row * 4096;
            const float* __restrict__ pB  = g_part + BB * K4 + row * 4096;
            const float* __restrict__ xgr = g_xg + ((size_t)t * 64 + row) * 4096;

            float gv[16];
            #pragma unroll
            for (int k = 0; k < 16; ++k) {
                const int c = tid + (k << 8);
                float v = pA[c] + pB[c] + xgr[c];
                gv[k] = v;
                brow[c] = v;
            }
            float s4[4] = {0.f, 0.f, 0.f, 0.f};
            #pragma unroll
            for (int k = 0; k < 16; ++k) s4[k >> 2] += gv[k];
            #pragma unroll
            for (int o = 16; o > 0; o >>= 1) {
                #pragma unroll
                for (int g = 0; g < 4; ++g) s4[g] += __shfl_xor_sync(0xFFFFFFFFu, s4[g], o);
            }
            if (lane == 0) {
                #pragma unroll
                for (int g = 0; g < 4; ++g) bred[warp * 4 + g] = s4[g];
            }
            __syncthreads();
            if (tid < 4) {
                float tot = 0.f;
                #pragma unroll
                for (int w = 0; w < 8; ++w) tot += bred[w * 4 + tid];
                bmu[tid] = tot * (1.0f / 1024.0f);
            }
            __syncthreads();
            const float mm[4] = {bmu[0], bmu[1], bmu[2], bmu[3]};
            float q4[4] = {0.f, 0.f, 0.f, 0.f};
            #pragma unroll
            for (int k = 0; k < 16; ++k) {
                float d = gv[k] - mm[k >> 2];
                q4[k >> 2] = fmaf(d, d, q4[k >> 2]);
            }
            #pragma unroll
            for (int o = 16; o > 0; o >>= 1) {
                #pragma unroll
                for (int g = 0; g < 4; ++g) q4[g] += __shfl_xor_sync(0xFFFFFFFFu, q4[g], o);
            }
            if (lane == 0) {
                #pragma unroll
                for (int g = 0; g < 4; ++g) bred[warp * 4 + g] = q4[g];
            }
            __syncthreads();
            if (tid < 4) {
                float tot = 0.f;
                #pragma unroll
                for (int w = 0; w < 8; ++w) tot += bred[w * 4 + tid];
                brs[tid] = rsqrtf(tot * (1.0f / 1024.0f) + 1e-5f);
            }
            __syncthreads();
            const float r0 = brs[0], r1 = brs[1], r2 = brs[2], r3 = brs[3];
            const float m0 = bmu[0], m1 = bmu[1], m2 = bmu[2], m3 = bmu[3];

            const int cbase = half * 512 + tid * 2;
            #pragma unroll
            for (int e = 0; e < 2; ++e) {
                const int c = cbase + e;
                float iv = (brow[c       ] - m0) * r0 * gamma[c       ] + beta[c       ];
                float fv = (brow[1024 + c] - m1) * r1 * gamma[1024 + c] + beta[1024 + c];
                float ov = (brow[2048 + c] - m2) * r2 * gamma[2048 + c] + beta[2048 + c];
                float uv = (brow[3072 + c] - m3) * r3 * gamma[3072 + c] + beta[3072 + c];
                float cp = g_c[row * 1024 + c];
                float cn = sigf(fv) * cp + sigf(iv) * tanhf(uv);
                float hn = sigf(ov) * tanhf(cn);
                g_c[row * 1024 + c] = cn;
                g_h[row * 1024 + c] = hn;
                ys[((size_t)t * 64 + row) * 1024 + c] = hn;
                if (t == SS - 1) {
                    outh[row * 1024 + c] = hn;
                    outc[row * 1024 + c] = cn;
                }
            }
        }

        grid_sync_(bid, gen);
    }
}

// ---------------- launch ----------------
extern "C" void kernel_launch(void* const* d_in, const int* in_sizes, int n_in,
                              void* d_out, int out_size)
{
    const float* inputs = (const float*)d_in[0];
    const float* h0     = (const float*)d_in[1];
    const float* c0     = (const float*)d_in[2];
    const float* wx     = (const float*)d_in[3];
    const float* wh     = (const float*)d_in[4];
    const float* bias   = (const float*)d_in[5];
    const float* gamma  = (const float*)d_in[6];
    const float* beta   = (const float*)d_in[7];

    float* out   = (float*)d_out;
    float* out_x = out;
    float* out_h = out + SBH;
    float* out_c = out_h + (size_t)LL * BH;

    static const int SCAN_SMEM = 131072 + 34816 + 256;
    cudaFuncSetAttribute(lstm_scan_kernel,
                         cudaFuncAttributeMaxDynamicSharedMemorySize, SCAN_SMEM);

    dim3 ggrid(K4 / 64, SB / 128);    // (64, 256)
    const int packBlocks = (512 * 4096) / 256;

    // Launch order chosen so launch index 5 (ncu -s 5 -c 1) is lstm_scan_kernel(l=0).
    pack_weights_kernel<<<packBlocks, 256>>>(wx, 0, 0);                        // [0]
    pack_weights_kernel<<<packBlocks, 256>>>(wh, 1, 0);                        // [1]
    init_state_kernel<<<(BH + 255) / 256, 256>>>(h0, c0);                      // [2]
    gemm_xg_kernel<<<ggrid, 256>>>(inputs, 0, bias);                           // [3]
    pack_weights_kernel<<<packBlocks, 256>>>(wh + (size_t)HH * K4, 1, 1);      // [4]
    lstm_scan_kernel<<<NBLK, 256, SCAN_SMEM>>>(gamma, beta, out_x, 0,          // [5] <- profiled
                                               out_h, out_c);
    pack_weights_kernel<<<packBlocks, 256>>>(wx + (size_t)DD * K4, 0, 1);      // [6]
    gemm_xg_kernel<<<ggrid, 256>>>(inputs, 1, bias + K4);                      // [7]
    init_state_kernel<<<(BH + 255) / 256, 256>>>(h0 + BH, c0 + BH);            // [8]
    lstm_scan_kernel<<<NBLK, 256, SCAN_SMEM>>>(gamma + 4 * HH, beta + 4 * HH,  // [9]
                                               out_x, 1,
                                               out_h + BH, out_c + BH);
}